// round 4
// baseline (speedup 1.0000x reference)
#include <cuda_runtime.h>

#define IC 1152
#define OC 10
#define ID 8
#define OD 16
#define BATCH 32
#define NI 8
#define NBLK (IC / NI)     // 144
#define THREADS 640        // 20 warps: thread = (c, b, od_half)
#define OUTSZ (BATCH * OC * OD)   // 5120

typedef unsigned long long ull;

__device__ float g_scratch[NBLK * OUTSZ];   // per-block partial outputs

__device__ __forceinline__ ull ffma2(ull a, ull b, ull c) {
    ull d; asm("fma.rn.f32x2 %0, %1, %2, %3;" : "=l"(d) : "l"(a), "l"(b), "l"(c)); return d;
}
__device__ __forceinline__ ull fmul2(ull a, ull b) {
    ull d; asm("mul.rn.f32x2 %0, %1, %2;" : "=l"(d) : "l"(a), "l"(b)); return d;
}
__device__ __forceinline__ ull fadd2(ull a, ull b) {
    ull d; asm("add.rn.f32x2 %0, %1, %2;" : "=l"(d) : "l"(a), "l"(b)); return d;
}
__device__ __forceinline__ ull pack2(float x, float y) {
    ull u; asm("mov.b64 %0, {%1, %2};" : "=l"(u) : "f"(x), "f"(y)); return u;
}
__device__ __forceinline__ void unpack2(ull u, float& x, float& y) {
    asm("mov.b64 {%0, %1}, %2;" : "=f"(x), "=f"(y) : "l"(u));
}
__device__ __forceinline__ float frcp(float x) {
    float y; asm("rcp.approx.f32 %0, %1;" : "=f"(y) : "f"(x)); return y;
}

__global__ __launch_bounds__(THREADS, 1) void caps_kernel(
    const float* __restrict__ x, const float* __restrict__ w, float* __restrict__ out_unused)
{
    __shared__ __align__(16) float ws_sm[OC * ID * OD];  // normalized weights ŵ
    __shared__ float wsum_sm[OC * ID];                   // per-(c,d) row sums
    __shared__ float xn_sm[ID][BATCH];                   // normalized x, [d][b]
    __shared__ float alpha_sm[OC * BATCH];

    const int t   = threadIdx.x;
    const int c   = t >> 6;          // output capsule: 2 warps per c
    const int b   = (t & 63) >> 1;   // batch
    const int odh = t & 1;           // od half: this thread owns od [odh*8, odh*8+8)
    const int i0  = blockIdx.x * NI;

    // ---- prefetch first i ----
    float2 wv = *(const float2*)(w + (size_t)i0 * (OC * ID * OD) + t * 2);
    float4 xv = make_float4(0.f, 0.f, 0.f, 0.f);
    if (t < 2 * BATCH) {
        int bb = t >> 1, half = t & 1;
        xv = *(const float4*)(x + ((size_t)bb * IC + i0) * ID + half * 4);
    }

    ull acc[4];
    #pragma unroll
    for (int j = 0; j < 4; j++) acc[j] = pack2(0.f, 0.f);

    #pragma unroll 1
    for (int ii = 0; ii < NI; ii++) {
        // ---- stage weights: each thread holds 2 od-values of row (c,d) = t/8 ----
        {
            float ps  = wv.x + wv.y;
            float tot = ps + __shfl_xor_sync(0xffffffffu, ps, 1);
            tot += __shfl_xor_sync(0xffffffffu, tot, 2);
            tot += __shfl_xor_sync(0xffffffffu, tot, 4);
            float r = frcp(tot);
            float2 wn; wn.x = wv.x * r; wn.y = wv.y * r;
            *(float2*)(ws_sm + t * 2) = wn;
            if ((t & 7) == 0) wsum_sm[t >> 3] = tot;
        }
        // ---- stage x: normalize over id, transpose to [d][b] ----
        if (t < 2 * BATCH) {
            int bb = t >> 1, half = t & 1;
            float ps  = xv.x + xv.y + xv.z + xv.w;
            float tot = ps + __shfl_xor_sync(0xffffffffu, ps, 1);
            float r = frcp(tot);
            xn_sm[half * 4 + 0][bb] = xv.x * r;
            xn_sm[half * 4 + 1][bb] = xv.y * r;
            xn_sm[half * 4 + 2][bb] = xv.z * r;
            xn_sm[half * 4 + 3][bb] = xv.w * r;
        }
        __syncthreads();

        // ---- prefetch next i ----
        if (ii + 1 < NI) {
            wv = *(const float2*)(w + (size_t)(i0 + ii + 1) * (OC * ID * OD) + t * 2);
            if (t < 2 * BATCH) {
                int bb = t >> 1, half = t & 1;
                xv = *(const float4*)(x + ((size_t)bb * IC + (i0 + ii + 1)) * ID + half * 4);
            }
        }

        const float* wc = ws_sm + c * (ID * OD) + odh * 8;  // this thread's od-half
        float xn[8];
        #pragma unroll
        for (int d = 0; d < 8; d++) xn[d] = xn_sm[d][b];

        // ---- iteration 1: h1[o] = Σ_d xn[d]·ŵ[d,o]  (h0 uniform) ----
        ull h[4];
        #pragma unroll
        for (int j = 0; j < 4; j++) h[j] = pack2(0.f, 0.f);
        #pragma unroll
        for (int d = 0; d < 8; d++) {
            ull xp = pack2(xn[d], xn[d]);
            const ulonglong2* wr = (const ulonglong2*)(wc + d * 16);
            ulonglong2 wa = wr[0], wb2 = wr[1];
            h[0] = ffma2(xp, wa.x,  h[0]);
            h[1] = ffma2(xp, wa.y,  h[1]);
            h[2] = ffma2(xp, wb2.x, h[2]);
            h[3] = ffma2(xp, wb2.y, h[3]);
        }

        // ---- iterations 2..5, fused den/f passes (scale-invariant ⇒ no renorm) ----
        #pragma unroll 1
        for (int it = 0; it < 4; it++) {
            ull f[4];
            #pragma unroll
            for (int j = 0; j < 4; j++) f[j] = pack2(0.f, 0.f);
            #pragma unroll
            for (int d = 0; d < 8; d++) {
                const ulonglong2* wr = (const ulonglong2*)(wc + d * 16);
                ulonglong2 wa = wr[0], wb2 = wr[1];
                ull p = fmul2(h[0], wa.x);
                p = ffma2(h[1], wa.y, p);
                ull q = fmul2(h[2], wb2.x);
                q = ffma2(h[3], wb2.y, q);
                p = fadd2(p, q);
                float pa, pb; unpack2(p, pa, pb);
                float hd  = pa + pb;                                   // half-dot
                float den = hd + __shfl_xor_sync(0xffffffffu, hd, 1);  // full od-dot
                float xr  = xn[d] * frcp(den);
                ull xp = pack2(xr, xr);
                f[0] = ffma2(xp, wa.x,  f[0]);
                f[1] = ffma2(xp, wa.y,  f[1]);
                f[2] = ffma2(xp, wb2.x, f[2]);
                f[3] = ffma2(xp, wb2.y, f[3]);
            }
            #pragma unroll
            for (int j = 0; j < 4; j++) h[j] = fmul2(h[j], f[j]);
        }

        // ---- epilogue: alpha from final denominators (reconstruct folded in) ----
        float A = 0.f;
        #pragma unroll
        for (int d = 0; d < 8; d++) {
            const ulonglong2* wr = (const ulonglong2*)(wc + d * 16);
            ulonglong2 wa = wr[0], wb2 = wr[1];
            ull p = fmul2(h[0], wa.x);
            p = ffma2(h[1], wa.y, p);
            ull q = fmul2(h[2], wb2.x);
            q = ffma2(h[3], wb2.y, q);
            p = fadd2(p, q);
            float pa, pb; unpack2(p, pa, pb);
            float hd  = pa + pb;
            float den = hd + __shfl_xor_sync(0xffffffffu, hd, 1);
            A += xn[d] * wsum_sm[c * 8 + d] * den;
        }
        ull s2 = fadd2(fadd2(h[0], h[1]), fadd2(h[2], h[3]));
        float sa, sb; unpack2(s2, sa, sb);
        float shh = sa + sb;
        float Sh  = shh + __shfl_xor_sync(0xffffffffu, shh, 1);
        float rSh = frcp(Sh);
        float ar  = A * rSh;                 // alpha (pre-normalization over c)
        if (odh == 0) alpha_sm[c * BATCH + b] = ar;
        __syncthreads();
        float S = 0.f;
        #pragma unroll
        for (int cc = 0; cc < OC; cc++) S += alpha_sm[cc * BATCH + b];
        float coeff = ar * frcp(S) * rSh;    // alpha_norm / Σh (h → hn folded in)
        ull cp = pack2(coeff, coeff);
        #pragma unroll
        for (int j = 0; j < 4; j++) acc[j] = ffma2(cp, h[j], acc[j]);
        __syncthreads();   // protect smem before next i's staging
    }

    // ---- per-block partials to scratch (coalesced STG, no atomics) ----
    float* dst = g_scratch + (size_t)blockIdx.x * OUTSZ + b * (OC * OD) + c * OD + odh * 8;
    ulonglong2 s0; s0.x = acc[0]; s0.y = acc[1];
    ulonglong2 s1; s1.x = acc[2]; s1.y = acc[3];
    ((ulonglong2*)dst)[0] = s0;
    ((ulonglong2*)dst)[1] = s1;
}

__global__ void caps_reduce_kernel(float* __restrict__ out) {
    int idx = blockIdx.x * blockDim.x + threadIdx.x;
    if (idx >= OUTSZ) return;
    float s = 0.f;
    #pragma unroll 4
    for (int k = 0; k < NBLK; k++) s += g_scratch[(size_t)k * OUTSZ + idx];
    out[idx] = s;
}

extern "C" void kernel_launch(void* const* d_in, const int* in_sizes, int n_in,
                              void* d_out, int out_size)
{
    const float* x = (const float*)d_in[0];
    const float* w = (const float*)d_in[1];
    if (n_in >= 2 && in_sizes[0] == IC * OC * ID * OD && in_sizes[1] == BATCH * IC * ID) {
        x = (const float*)d_in[1];
        w = (const float*)d_in[0];
    }
    float* out = (float*)d_out;

    caps_kernel<<<NBLK, THREADS>>>(x, w, out);
    caps_reduce_kernel<<<(OUTSZ + 255) / 256, 256>>>(out);
}

// round 5
// speedup vs baseline: 1.2178x; 1.2178x over previous
#include <cuda_runtime.h>

#define IC 1152
#define OC 10
#define ID 8
#define OD 16
#define BATCH 32
#define NI 8
#define NBLK (IC / NI)     // 144
#define THREADS 640        // 20 warps: thread = (c, b, od_half)
#define OUTSZ (BATCH * OC * OD)   // 5120

typedef unsigned long long ull;

__device__ float g_scratch[NBLK * OUTSZ];   // per-block partial outputs

__device__ __forceinline__ ull ffma2(ull a, ull b, ull c) {
    ull d; asm("fma.rn.f32x2 %0, %1, %2, %3;" : "=l"(d) : "l"(a), "l"(b), "l"(c)); return d;
}
__device__ __forceinline__ ull fmul2(ull a, ull b) {
    ull d; asm("mul.rn.f32x2 %0, %1, %2;" : "=l"(d) : "l"(a), "l"(b)); return d;
}
__device__ __forceinline__ ull fadd2(ull a, ull b) {
    ull d; asm("add.rn.f32x2 %0, %1, %2;" : "=l"(d) : "l"(a), "l"(b)); return d;
}
__device__ __forceinline__ ull pack2(float x, float y) {
    ull u; asm("mov.b64 %0, {%1, %2};" : "=l"(u) : "f"(x), "f"(y)); return u;
}
__device__ __forceinline__ void unpack2(ull u, float& x, float& y) {
    asm("mov.b64 {%0, %1}, %2;" : "=f"(x), "=f"(y) : "l"(u));
}
__device__ __forceinline__ float frcp(float x) {
    float y; asm("rcp.approx.f32 %0, %1;" : "=f"(y) : "f"(x)); return y;
}

__global__ __launch_bounds__(THREADS, 1) void caps_kernel(
    const float* __restrict__ x, const float* __restrict__ w, float* __restrict__ out_unused)
{
    __shared__ __align__(16) float ws_sm[OC * ID * OD];  // normalized weights ŵ
    __shared__ float wsum_sm[OC * ID];                   // per-(c,d) row sums
    __shared__ float xn_sm[ID][BATCH];                   // normalized x, [d][b]
    __shared__ float alpha_sm[OC * BATCH];

    const int t   = threadIdx.x;
    const int c   = t >> 6;          // output capsule: 2 warps per c
    const int b   = (t & 63) >> 1;   // batch
    const int odh = t & 1;           // od half: this thread owns od [odh*8, odh*8+8)
    const int i0  = blockIdx.x * NI;

    // ---- prefetch first i ----
    float2 wv = *(const float2*)(w + (size_t)i0 * (OC * ID * OD) + t * 2);
    float4 xv = make_float4(0.f, 0.f, 0.f, 0.f);
    if (t < 2 * BATCH) {
        int bb = t >> 1, half = t & 1;
        xv = *(const float4*)(x + ((size_t)bb * IC + i0) * ID + half * 4);
    }

    ull acc[4];
    #pragma unroll
    for (int j = 0; j < 4; j++) acc[j] = pack2(0.f, 0.f);

    #pragma unroll 1
    for (int ii = 0; ii < NI; ii++) {
        // ---- stage weights: each thread holds 2 od-values of row (c,d) = t/8 ----
        {
            float ps  = wv.x + wv.y;
            float tot = ps + __shfl_xor_sync(0xffffffffu, ps, 1);
            tot += __shfl_xor_sync(0xffffffffu, tot, 2);
            tot += __shfl_xor_sync(0xffffffffu, tot, 4);
            float r = frcp(tot);
            float2 wn; wn.x = wv.x * r; wn.y = wv.y * r;
            *(float2*)(ws_sm + t * 2) = wn;
            if ((t & 7) == 0) wsum_sm[t >> 3] = tot;
        }
        // ---- stage x: normalize over id, transpose to [d][b] ----
        if (t < 2 * BATCH) {
            int bb = t >> 1, half = t & 1;
            float ps  = xv.x + xv.y + xv.z + xv.w;
            float tot = ps + __shfl_xor_sync(0xffffffffu, ps, 1);
            float r = frcp(tot);
            xn_sm[half * 4 + 0][bb] = xv.x * r;
            xn_sm[half * 4 + 1][bb] = xv.y * r;
            xn_sm[half * 4 + 2][bb] = xv.z * r;
            xn_sm[half * 4 + 3][bb] = xv.w * r;
        }
        __syncthreads();

        // ---- prefetch next i ----
        if (ii + 1 < NI) {
            wv = *(const float2*)(w + (size_t)(i0 + ii + 1) * (OC * ID * OD) + t * 2);
            if (t < 2 * BATCH) {
                int bb = t >> 1, half = t & 1;
                xv = *(const float4*)(x + ((size_t)bb * IC + (i0 + ii + 1)) * ID + half * 4);
            }
        }

        const float* wc = ws_sm + c * (ID * OD) + odh * 8;  // this thread's od-half
        float xn[8];
        #pragma unroll
        for (int d = 0; d < 8; d++) xn[d] = xn_sm[d][b];

        // ---- iteration 1: h1[o] = Σ_d xn[d]·ŵ[d,o]  (h0 uniform) ----
        ull h[4];
        #pragma unroll
        for (int j = 0; j < 4; j++) h[j] = pack2(0.f, 0.f);
        #pragma unroll
        for (int d = 0; d < 8; d++) {
            ull xp = pack2(xn[d], xn[d]);
            const ulonglong2* wr = (const ulonglong2*)(wc + d * 16);
            ulonglong2 wa = wr[0], wb2 = wr[1];
            h[0] = ffma2(xp, wa.x,  h[0]);
            h[1] = ffma2(xp, wa.y,  h[1]);
            h[2] = ffma2(xp, wb2.x, h[2]);
            h[3] = ffma2(xp, wb2.y, h[3]);
        }

        // ---- iterations 2..5, fused den/f passes (scale-invariant ⇒ no renorm) ----
        #pragma unroll 1
        for (int it = 0; it < 4; it++) {
            ull f[4];
            #pragma unroll
            for (int j = 0; j < 4; j++) f[j] = pack2(0.f, 0.f);
            #pragma unroll
            for (int d = 0; d < 8; d++) {
                const ulonglong2* wr = (const ulonglong2*)(wc + d * 16);
                ulonglong2 wa = wr[0], wb2 = wr[1];
                ull p = fmul2(h[0], wa.x);
                p = ffma2(h[1], wa.y, p);
                ull q = fmul2(h[2], wb2.x);
                q = ffma2(h[3], wb2.y, q);
                p = fadd2(p, q);
                float pa, pb; unpack2(p, pa, pb);
                float hd  = pa + pb;                                   // half-dot
                float den = hd + __shfl_xor_sync(0xffffffffu, hd, 1);  // full od-dot
                float xr  = xn[d] * frcp(den);
                ull xp = pack2(xr, xr);
                f[0] = ffma2(xp, wa.x,  f[0]);
                f[1] = ffma2(xp, wa.y,  f[1]);
                f[2] = ffma2(xp, wb2.x, f[2]);
                f[3] = ffma2(xp, wb2.y, f[3]);
            }
            #pragma unroll
            for (int j = 0; j < 4; j++) h[j] = fmul2(h[j], f[j]);
        }

        // ---- epilogue: alpha from final denominators (reconstruct folded in) ----
        float A = 0.f;
        #pragma unroll
        for (int d = 0; d < 8; d++) {
            const ulonglong2* wr = (const ulonglong2*)(wc + d * 16);
            ulonglong2 wa = wr[0], wb2 = wr[1];
            ull p = fmul2(h[0], wa.x);
            p = ffma2(h[1], wa.y, p);
            ull q = fmul2(h[2], wb2.x);
            q = ffma2(h[3], wb2.y, q);
            p = fadd2(p, q);
            float pa, pb; unpack2(p, pa, pb);
            float hd  = pa + pb;
            float den = hd + __shfl_xor_sync(0xffffffffu, hd, 1);
            A += xn[d] * wsum_sm[c * 8 + d] * den;
        }
        ull s2 = fadd2(fadd2(h[0], h[1]), fadd2(h[2], h[3]));
        float sa, sb; unpack2(s2, sa, sb);
        float shh = sa + sb;
        float Sh  = shh + __shfl_xor_sync(0xffffffffu, shh, 1);
        float rSh = frcp(Sh);
        float ar  = A * rSh;                 // alpha (pre-normalization over c)
        if (odh == 0) alpha_sm[c * BATCH + b] = ar;
        __syncthreads();
        float S = 0.f;
        #pragma unroll
        for (int cc = 0; cc < OC; cc++) S += alpha_sm[cc * BATCH + b];
        float coeff = ar * frcp(S) * rSh;    // alpha_norm / Σh (h → hn folded in)
        ull cp = pack2(coeff, coeff);
        #pragma unroll
        for (int j = 0; j < 4; j++) acc[j] = ffma2(cp, h[j], acc[j]);
        __syncthreads();   // protect smem before next i's staging
    }

    // ---- per-block partials to scratch (coalesced STG, no atomics) ----
    float* dst = g_scratch + (size_t)blockIdx.x * OUTSZ + b * (OC * OD) + c * OD + odh * 8;
    ulonglong2 s0; s0.x = acc[0]; s0.y = acc[1];
    ulonglong2 s1; s1.x = acc[2]; s1.y = acc[3];
    ((ulonglong2*)dst)[0] = s0;
    ((ulonglong2*)dst)[1] = s1;
}

// Parallel reduce: grid = 160 blocks x 128 threads.
// thread = (ks = tid/32 in 0..3, lane -> outidx). Each thread sums 36
// fully-unrolled independent loads (MLP~36, coalesced 128B per warp),
// then a 4-way smem combine writes the final output element.
#define KSLICE 36   // 144 / 4
__global__ __launch_bounds__(128, 8) void caps_reduce_kernel(float* __restrict__ out) {
    __shared__ float red[4][32];
    const int lane = threadIdx.x & 31;
    const int ks   = threadIdx.x >> 5;
    const int j    = blockIdx.x * 32 + lane;   // output index (5120 total)

    const float* src = g_scratch + (size_t)(ks * KSLICE) * OUTSZ + j;
    float s = 0.f;
    #pragma unroll
    for (int k = 0; k < KSLICE; k++) s += src[(size_t)k * OUTSZ];

    red[ks][lane] = s;
    __syncthreads();
    if (ks == 0) {
        out[j] = red[0][lane] + red[1][lane] + red[2][lane] + red[3][lane];
    }
}

extern "C" void kernel_launch(void* const* d_in, const int* in_sizes, int n_in,
                              void* d_out, int out_size)
{
    const float* x = (const float*)d_in[0];
    const float* w = (const float*)d_in[1];
    if (n_in >= 2 && in_sizes[0] == IC * OC * ID * OD && in_sizes[1] == BATCH * IC * ID) {
        x = (const float*)d_in[1];
        w = (const float*)d_in[0];
    }
    float* out = (float*)d_out;

    caps_kernel<<<NBLK, THREADS>>>(x, w, out);
    caps_reduce_kernel<<<OUTSZ / 32, 128>>>(out);
}